// round 17
// baseline (speedup 1.0000x reference)
#include <cuda_runtime.h>
#include <math.h>
#include <stdint.h>

#define BATCH 64
#define NG    32
#define CIN   128
#define COUT  128
#define LMAX  16
#define NR    (BATCH*LMAX*2)   // 2048 rows (b,m,ri)

typedef unsigned long long u64;
#define NEGM 0x8000000080000000ULL

__device__ __forceinline__ u64 f2u(float x, float y) {
    u64 r; asm("mov.b64 %0,{%1,%2};" : "=l"(r) : "f"(x), "f"(y)); return r;
}
__device__ __forceinline__ u64 add2(u64 a, u64 b) {
    u64 r; asm("add.rn.f32x2 %0,%1,%2;" : "=l"(r) : "l"(a), "l"(b)); return r;
}
__device__ __forceinline__ u64 fma2_(u64 a, u64 b, u64 c) {
    u64 r; asm("fma.rn.f32x2 %0,%1,%2,%3;" : "=l"(r) : "l"(a), "l"(b), "l"(c)); return r;
}

// ---------------- scratch (device globals; no allocation allowed) ----------
__device__ float g_F[(size_t)BATCH*LMAX*2*NG*CIN];     // [b][m][ri][j][i]
// coef/chat layout: [l][m][ri][b][c]  -> valid region per l = first (l+1)*128 rows
__device__ float g_coef[(size_t)LMAX*2048*CIN];
__device__ float g_chat[(size_t)LMAX*2048*COUT];
__device__ float g_G[(size_t)BATCH*NG*LMAX*2*COUT];    // [b][j][m][ri][o]
__device__ float g_Qw[LMAX*LMAX*NG];                   // [l][m][j] * wj * s_l
__device__ float g_Qs[LMAX*LMAX*NG];                   // [l][m][j] * k_m
__device__ float g_cosT[LMAX*NG];                      // [m][p]
__device__ float g_sinT[LMAX*NG];

// kC smem geometry (floats)
#define APAD 132
#define BPAD 136
#define SM_A_FLOATS (128*APAD)
#define SM_B_FLOATS (128*BPAD)
#define SM_C_BYTES  ((SM_A_FLOATS + SM_B_FLOATS) * 4)   // 137216

__device__ __forceinline__ float to_tf32(float x) {
    float r;
    asm("cvt.rna.tf32.f32 %0, %1;" : "=f"(r) : "f"(x));
    return r;
}

#define MMA_TF32(acc, a, b0, b1)                                          \
    asm volatile(                                                         \
        "mma.sync.aligned.m16n8k8.row.col.f32.tf32.tf32.f32 "             \
        "{%0,%1,%2,%3}, {%4,%5,%6,%7}, {%8,%9}, {%0,%1,%2,%3};"           \
        : "+f"((acc)[0]), "+f"((acc)[1]), "+f"((acc)[2]), "+f"((acc)[3])  \
        : "r"((a)[0]), "r"((a)[1]), "r"((a)[2]), "r"((a)[3]),             \
          "r"(b0), "r"(b1))

// ---------------- init: Legendre + trig tables, fp32, 512-way parallel -----
__global__ void init_tables() {
    int t = threadIdx.x;                  // 0..511
    int m = t >> 5, j = t & 31;           // one thread per (m, j)
    float sx, cx;
    sincospif((j + 0.5f) / NG, &sx, &cx);
    float wj = sx * ((float)M_PI / NG) * (2.0f * (float)M_PI / NG);

    for (int l = 0; l < m; l++) {
        g_Qw[(l*LMAX + m)*NG + j] = 0.f;
        g_Qs[(l*LMAX + m)*NG + j] = 0.f;
    }

    float Pmm = 1.0f, invf = 1.0f;
    for (int mm = 1; mm <= m; mm++) Pmm = -(2.0f*mm - 1.0f) * sx * Pmm;
    for (int tt = 1; tt <= 2*m; tt++) invf /= (float)tt;
    float rat = invf;
    float pl_2 = 0.0f, pl_1 = 0.0f, pl = 0.0f;
    const float inv4pi = 1.0f / (4.0f * (float)M_PI);
    for (int l = m; l < LMAX; l++) {
        if (l == m)        pl = Pmm;
        else if (l == m+1) pl = (2.0f*m + 1.0f) * cx * Pmm;
        else               pl = ((2.0f*l - 1.0f)*cx*pl_1 - (l + m - 1.0f)*pl_2) / (float)(l - m);
        float Nlm = sqrtf((2.0f*l + 1.0f) * inv4pi * rat);
        float q   = Nlm * pl;
        float sl  = 2.0f*(float)M_PI * sqrtf(4.0f*(float)M_PI / (2.0f*l + 1.0f));
        float km  = (m == 0) ? 1.0f : 2.0f;
        g_Qw[(l*LMAX + m)*NG + j] = q * wj * sl;
        g_Qs[(l*LMAX + m)*NG + j] = q * km;
        pl_2 = pl_1; pl_1 = pl;
        rat *= (float)(l + 1 - m) / (float)(l + 1 + m);
    }

    float sa, ca;
    sincospif(2.0f * (float)m * (float)j / (float)NG, &sa, &ca);
    g_cosT[m*NG + j] = ca;
    g_sinT[m*NG + j] = sa;
}

// ---------------- A: real DFT over phi (half-split), FFMA2 -----------------
__global__ void __launch_bounds__(64) kA(const float* __restrict__ in) {
    int bj = blockIdx.x;                  // b*32 + j (theta)
    int b = bj >> 5, j = bj & 31;
    int t = threadIdx.x;                  // channel pair 0..63
    __shared__ u64 tcc[16][16], tsn[16][16];   // (c,c), (-s,-s)
    for (int q = t; q < 256; q += 64) {
        int m = q >> 4, p = q & 15;
        float c = g_cosT[m*NG + p], s = g_sinT[m*NG + p];
        tcc[m][p] = f2u(c, c);
        tsn[m][p] = f2u(-s, -s);
    }
    __syncthreads();

    const u64* src = (const u64*)in + (size_t)bj * NG * 64 + t;
    u64 xe[16], xo[16];
#pragma unroll
    for (int p = 0; p < 16; p++) {
        u64 a = src[p*64], c = src[(p+16)*64];
        xe[p] = add2(a, c);
        xo[p] = add2(a, c ^ NEGM);
    }

    u64* Fout = (u64*)g_F;
#pragma unroll
    for (int m = 0; m < 16; m++) {
        u64 fr = 0, fi = 0;               // packed (+0,+0)
#pragma unroll
        for (int p = 0; p < 16; p++) {
            u64 x = (m & 1) ? xo[p] : xe[p];
            fr = fma2_(x, tcc[m][p], fr);
            fi = fma2_(x, tsn[m][p], fi);
        }
        size_t base = ((((size_t)b*16 + m)*2 + 0)*NG + j)*64 + t;
        Fout[base]         = fr;
        Fout[base + NG*64] = fi;          // ri=1
    }
}

// ---------------- B: Legendre analysis with reflection, FFMA2 --------------
__global__ void __launch_bounds__(64) kB() {
    int r = blockIdx.x;                   // (b*16+m)*2+ri
    int b = r >> 5, m = (r >> 1) & 15, ri = r & 1;
    int t = threadIdx.x;
    __shared__ u64 sq[16][16];            // (q,q) dup of Qw[l][m][j], j<16
    for (int q = t; q < 256; q += 64) {
        int l = q >> 4, j = q & 15;
        float v = g_Qw[(l*LMAX + m)*NG + j];
        sq[l][j] = f2u(v, v);
    }
    __syncthreads();

    const u64* src = (const u64*)g_F + (size_t)r * NG * 64 + t;
    u64 fe[16], fo[16];
#pragma unroll
    for (int j = 0; j < 16; j++) {
        u64 a = src[j*64], c = src[(31-j)*64];
        fe[j] = add2(a, c);
        fo[j] = add2(a, c ^ NEGM);
    }

    u64* Cout = (u64*)g_coef;
    size_t rowbase = (size_t)(m*2 + ri)*64 + b;   // within-l row offset
    if ((m & 1) == 0) {
#pragma unroll
        for (int l = 0; l < 16; l++) {
            if (l < m) continue;
            u64 acc = 0;
#pragma unroll
            for (int j = 0; j < 16; j++)
                acc = fma2_(sq[l][j], (l & 1) ? fo[j] : fe[j], acc);
            Cout[((size_t)l*2048 + rowbase)*64 + t] = acc;
        }
    } else {
#pragma unroll
        for (int l = 0; l < 16; l++) {
            if (l < m) continue;
            u64 acc = 0;
#pragma unroll
            for (int j = 0; j < 16; j++)
                acc = fma2_(sq[l][j], (l & 1) ? fe[j] : fo[j], acc);
            Cout[((size_t)l*2048 + rowbase)*64 + t] = acc;
        }
    }
}

// ---------------- C: per-degree channel mix on tensor cores (tf32 mma) -----
__global__ void __launch_bounds__(256) kC(const float* __restrict__ w) {
    int l = blockIdx.y, mt = blockIdx.x;
    if (mt > l) return;                   // zero region: skip
    extern __shared__ float sm[];
    float* As = sm;                       // [128][APAD]
    float* Bs = sm + SM_A_FLOATS;         // [128][BPAD]

    const float* A = g_coef + ((size_t)l*2048 + (size_t)mt*128)*CIN;
    const float* B = w + l*COUT;
    float* C = g_chat + ((size_t)l*2048 + (size_t)mt*128)*COUT;

    int tid = threadIdx.x;
#pragma unroll
    for (int e = 0; e < 16; e++) {
        int lin = tid + e*256;
        int row = lin >> 5, c4 = lin & 31;
        float4 va = *(const float4*)&A[row*CIN + c4*4];
        float* d = &As[row*APAD + c4*4];
        d[0] = to_tf32(va.x); d[1] = to_tf32(va.y);
        d[2] = to_tf32(va.z); d[3] = to_tf32(va.w);
        float4 vb = *(const float4*)&B[(size_t)row*(LMAX*COUT) + c4*4];
        float* db = &Bs[row*BPAD + c4*4];
        db[0] = to_tf32(vb.x); db[1] = to_tf32(vb.y);
        db[2] = to_tf32(vb.z); db[3] = to_tf32(vb.w);
    }
    __syncthreads();

    int wid = tid >> 5, lane = tid & 31;
    int g = lane >> 2, tg = lane & 3;
    int wm = wid & 3, wn = wid >> 2;
    int rbase = wm*32, cbase = wn*64;

    float acc[2][8][4];
#pragma unroll
    for (int mf = 0; mf < 2; mf++)
#pragma unroll
        for (int nf = 0; nf < 8; nf++)
#pragma unroll
            for (int q = 0; q < 4; q++) acc[mf][nf][q] = 0.f;

    const uint32_t* Au = (const uint32_t*)As;
    const uint32_t* Bu = (const uint32_t*)Bs;

#pragma unroll
    for (int ks = 0; ks < 16; ks++) {
        int k0 = ks*8;
        uint32_t a[2][4];
#pragma unroll
        for (int mf = 0; mf < 2; mf++) {
            int r0 = rbase + mf*16;
            a[mf][0] = Au[(r0 + g    )*APAD + k0 + tg    ];
            a[mf][1] = Au[(r0 + g + 8)*APAD + k0 + tg    ];
            a[mf][2] = Au[(r0 + g    )*APAD + k0 + tg + 4];
            a[mf][3] = Au[(r0 + g + 8)*APAD + k0 + tg + 4];
        }
#pragma unroll
        for (int nf = 0; nf < 8; nf++) {
            int c0 = cbase + nf*8 + g;
            uint32_t b0 = Bu[(k0 + tg    )*BPAD + c0];
            uint32_t b1 = Bu[(k0 + tg + 4)*BPAD + c0];
            MMA_TF32(acc[0][nf], a[0], b0, b1);
            MMA_TF32(acc[1][nf], a[1], b0, b1);
        }
    }

#pragma unroll
    for (int mf = 0; mf < 2; mf++) {
        int r0 = rbase + mf*16 + g;
#pragma unroll
        for (int nf = 0; nf < 8; nf++) {
            int c0 = cbase + nf*8 + tg*2;
            *(float2*)&C[(size_t)r0*COUT + c0] =
                make_float2(acc[mf][nf][0], acc[mf][nf][1]);
            *(float2*)&C[(size_t)(r0 + 8)*COUT + c0] =
                make_float2(acc[mf][nf][2], acc[mf][nf][3]);
        }
    }
}

// ---------------- D: Legendre synthesis with reflection, FFMA2 -------------
__global__ void __launch_bounds__(64) kD() {
    int r = blockIdx.x;                   // (b*16+m)*2+ri
    int ri = r & 1, m = (r >> 1) & 15, b = r >> 5;
    int t = threadIdx.x;
    __shared__ u64 sq[16][16];            // (q,q) dup of Qs[l][m][j]
    for (int q = t; q < 256; q += 64) {
        int l = q >> 4, j = q & 15;
        float v = g_Qs[(l*LMAX + m)*NG + j];
        sq[l][j] = f2u(v, v);
    }
    __syncthreads();

    u64 ch[16];
    const u64* src = (const u64*)g_chat;
    size_t rowbase = (size_t)(m*2 + ri)*64 + b;
#pragma unroll
    for (int l = 0; l < 16; l++)
        ch[l] = (l >= m) ? src[((size_t)l*2048 + rowbase)*64 + t] : 0ULL;

    u64* Gout = (u64*)g_G;
    size_t gbase = ((((size_t)b*NG)*16 + m)*2 + ri)*64 + t;
    const size_t jstride = (size_t)16*2*64;

    if ((m & 1) == 0) {
#pragma unroll
        for (int j = 0; j < 16; j++) {
            u64 Ge = 0, Go = 0;
#pragma unroll
            for (int l = 0; l < 16; l++) {
                if (l & 1) Go = fma2_(sq[l][j], ch[l], Go);
                else       Ge = fma2_(sq[l][j], ch[l], Ge);
            }
            Gout[gbase + (size_t)j*jstride]      = add2(Ge, Go);
            Gout[gbase + (size_t)(31-j)*jstride] = add2(Ge, Go ^ NEGM);
        }
    } else {
#pragma unroll
        for (int j = 0; j < 16; j++) {
            u64 Ge = 0, Go = 0;
#pragma unroll
            for (int l = 0; l < 16; l++) {
                if (l & 1) Ge = fma2_(sq[l][j], ch[l], Ge);
                else       Go = fma2_(sq[l][j], ch[l], Go);
            }
            Gout[gbase + (size_t)j*jstride]      = add2(Ge, Go);
            Gout[gbase + (size_t)(31-j)*jstride] = add2(Ge, Go ^ NEGM);
        }
    }
}

// ---------------- E: inverse real DFT over phi (half-split) + bias, FFMA2 --
__global__ void __launch_bounds__(64) kE(const float* __restrict__ bias,
                                         float* __restrict__ out) {
    int bj = blockIdx.x;                  // b*32 + j (theta)
    int t = threadIdx.x;                  // channel pair
    __shared__ u64 tcc[16][16], tsn[16][16];
    for (int q = t; q < 256; q += 64) {
        int m = q >> 4, p = q & 15;
        float c = g_cosT[m*NG + p], s = g_sinT[m*NG + p];
        tcc[m][p] = f2u(c, c);
        tsn[m][p] = f2u(-s, -s);
    }
    __syncthreads();

    u64 gr[16], gi[16];
    const u64* src = (const u64*)g_G + (size_t)bj * 16 * 2 * 64 + t;
#pragma unroll
    for (int m = 0; m < 16; m++) {
        gr[m] = src[(m*2 + 0)*64];
        gi[m] = src[(m*2 + 1)*64];
    }
    u64 bv = ((const u64*)bias)[t];
    u64* dst = (u64*)out + (size_t)bj * NG * 64 + t;
#pragma unroll
    for (int p = 0; p < 16; p++) {
        u64 E = 0, O = 0;
#pragma unroll
        for (int m = 0; m < 16; m++) {
            if (m & 1) {
                O = fma2_(gr[m], tcc[m][p], O);
                O = fma2_(gi[m], tsn[m][p], O);
            } else {
                E = fma2_(gr[m], tcc[m][p], E);
                E = fma2_(gi[m], tsn[m][p], E);
            }
        }
        u64 be = add2(bv, E);
        dst[p*64]      = add2(be, O);
        dst[(p+16)*64] = add2(be, O ^ NEGM);
    }
}

extern "C" void kernel_launch(void* const* d_in, const int* in_sizes, int n_in,
                              void* d_out, int out_size) {
    const float* in   = (const float*)d_in[0];
    const float* w    = (const float*)d_in[1];
    const float* bias = (const float*)d_in[2];
    float* out = (float*)d_out;

    cudaFuncSetAttribute(kC, cudaFuncAttributeMaxDynamicSharedMemorySize, SM_C_BYTES);

    init_tables<<<1, 512>>>();
    kA<<<BATCH*NG, 64>>>(in);
    kB<<<NR, 64>>>();
    kC<<<dim3(16, LMAX), 256, SM_C_BYTES>>>(w);
    kD<<<NR, 64>>>();
    kE<<<BATCH*NG, 64>>>(bias, out);
}